// round 5
// baseline (speedup 1.0000x reference)
#include <cuda_runtime.h>
#include <math.h>

#define Nn 100000
#define Ee 1200000

// ---------------- persistent device scratch (no runtime allocation) ----------------
__device__ int    d_is64;          // 1 if edge indices are int64, 0 if int32
__device__ int    d_cnt[2][Nn];
__device__ int    d_rowstart[2][Nn + 1];
__device__ int    d_cursor[2][Nn];
__device__ int    d_csr[2][Ee];
__device__ float  d_inv[2][Nn];
__device__ int    d_bsum[2][128];
__device__ int    d_bscan[2][128];
__device__ float4 d_P[Nn * 32];    // pos-mean-agg of current features (128 f32 per node)
__device__ float4 d_Q[Nn * 32];    // neg-mean-agg
__device__ float4 d_Z1[Nn * 32];   // z after round 0
__device__ float4 d_Z2[Nn * 32];   // z after round 1

// ---------------- dtype detection ----------------
// If the buffer really holds int64 indices (all < 2^31, nonnegative), then viewed
// as int32 every odd word is 0. With int32 data, 1024 sampled odd-position words
// being ALL zero has probability ~(1e-5)^1024 — impossible.
__global__ void k_detect(const int* __restrict__ pe) {
    __shared__ int nz;
    if (threadIdx.x == 0) nz = 0;
    __syncthreads();
    // sample odd positions spread over the first 2*1024 int32 words (always in-bounds:
    // buffer has at least 2*Ee int32 words in either dtype interpretation)
    for (int t = threadIdx.x; t < 1024; t += blockDim.x) {
        if (pe[2 * t + 1] != 0) nz = 1;
    }
    __syncthreads();
    if (threadIdx.x == 0) d_is64 = (nz == 0) ? 1 : 0;
}

__device__ __forceinline__ int edge_at(const void* p, long i, int is64) {
    return is64 ? (int)((const long long*)p)[i] : ((const int*)p)[i];
}

// ---------------- CSR build ----------------
__global__ void k_zero() {
    int i = blockIdx.x * blockDim.x + threadIdx.x;
    if (i < 2 * Nn) (&d_cnt[0][0])[i] = 0;
}

__global__ void k_hist(const void* __restrict__ pe, const void* __restrict__ ne) {
    int is64 = d_is64;
    int i = blockIdx.x * blockDim.x + threadIdx.x;
    if (i < Ee) {
        int dst = edge_at(pe, (long)Ee + i, is64);
        if ((unsigned)dst < Nn) atomicAdd(&d_cnt[0][dst], 1);
    } else if (i < 2 * Ee) {
        int dst = edge_at(ne, (long)i, is64);   // i in [Ee,2Ee) indexes ne's dst row
        if ((unsigned)dst < Nn) atomicAdd(&d_cnt[1][dst], 1);
    }
}

__global__ void k_scan1() {
    __shared__ int sh[1024];
    int L = blockIdx.y;
    int i = blockIdx.x * 1024 + threadIdx.x;
    int v = (i < Nn) ? d_cnt[L][i] : 0;
    sh[threadIdx.x] = v;
    __syncthreads();
    for (int off = 1; off < 1024; off <<= 1) {
        int t = (threadIdx.x >= off) ? sh[threadIdx.x - off] : 0;
        __syncthreads();
        sh[threadIdx.x] += t;
        __syncthreads();
    }
    if (i < Nn) d_rowstart[L][i] = sh[threadIdx.x] - v;   // partial exclusive
    if (threadIdx.x == 1023) d_bsum[L][blockIdx.x] = sh[1023];
}

__global__ void k_scan2() {
    __shared__ int sh[128];
    int L = blockIdx.y;
    int v = (threadIdx.x < 98) ? d_bsum[L][threadIdx.x] : 0;
    sh[threadIdx.x] = v;
    __syncthreads();
    for (int off = 1; off < 128; off <<= 1) {
        int t = (threadIdx.x >= off) ? sh[threadIdx.x - off] : 0;
        __syncthreads();
        sh[threadIdx.x] += t;
        __syncthreads();
    }
    d_bscan[L][threadIdx.x] = sh[threadIdx.x] - v;        // exclusive
}

__global__ void k_scan3() {
    int L = blockIdx.y;
    int i = blockIdx.x * blockDim.x + threadIdx.x;
    if (i < Nn) {
        int rs = d_rowstart[L][i] + d_bscan[L][i >> 10];
        d_rowstart[L][i] = rs;
        d_cursor[L][i]   = rs;
        int c = d_cnt[L][i];
        d_inv[L][i] = 1.0f / (float)(c > 0 ? c : 1);
        if (i == 0) d_rowstart[L][Nn] = rs + 0;  // placeholder; fixed below
    }
    // total edge count per list: rowstart[Nn] = rowstart[Nn-1] + cnt[Nn-1]
    if (i == Nn - 1) d_rowstart[L][Nn] = d_rowstart[L][i] + d_cnt[L][i];
}

__global__ void k_fill(const void* __restrict__ pe, const void* __restrict__ ne) {
    int is64 = d_is64;
    int i = blockIdx.x * blockDim.x + threadIdx.x;
    if (i < Ee) {
        int s = edge_at(pe, (long)i, is64);
        int d = edge_at(pe, (long)Ee + i, is64);
        if ((unsigned)d < Nn && (unsigned)s < Nn)
            d_csr[0][atomicAdd(&d_cursor[0][d], 1)] = s;
    } else if (i < 2 * Ee) {
        long k = i - Ee;
        int s = edge_at(ne, k, is64);
        int d = edge_at(ne, (long)i, is64);
        if ((unsigned)d < Nn && (unsigned)s < Nn)
            d_csr[1][atomicAdd(&d_cursor[1][d], 1)] = s;
    }
}

// ---------------- per-destination mean aggregation (atomic-free) ----------------
// grid (Nn/4, 2), block 128: warp per dst node, lane = float4 column.
__global__ void k_agg(const float4* __restrict__ ext, int io) {
    const float4* __restrict__ Zin = (io == 0) ? ext
                                   : (io == 1 ? (const float4*)d_Z1 : (const float4*)d_Z2);
    int L    = blockIdx.y;
    int node = blockIdx.x * 4 + (threadIdx.x >> 5);
    int lane = threadIdx.x & 31;
    int s = d_rowstart[L][node];
    int e = d_rowstart[L][node + 1];
    const int* __restrict__ csr = d_csr[L];
    float ax = 0.f, ay = 0.f, az = 0.f, aw = 0.f;
    int j = s;
    for (; j + 4 <= e; j += 4) {
        int s0 = csr[j], s1 = csr[j + 1], s2 = csr[j + 2], s3 = csr[j + 3];
        float4 v0 = Zin[s0 * 32 + lane];
        float4 v1 = Zin[s1 * 32 + lane];
        float4 v2 = Zin[s2 * 32 + lane];
        float4 v3 = Zin[s3 * 32 + lane];
        ax += v0.x + v1.x + v2.x + v3.x;
        ay += v0.y + v1.y + v2.y + v3.y;
        az += v0.z + v1.z + v2.z + v3.z;
        aw += v0.w + v1.w + v2.w + v3.w;
    }
    for (; j < e; j++) {
        float4 v = Zin[csr[j] * 32 + lane];
        ax += v.x; ay += v.y; az += v.z; aw += v.w;
    }
    float iv = d_inv[L][node];
    (L ? d_Q : d_P)[node * 32 + lane] = make_float4(ax * iv, ay * iv, az * iv, aw * iv);
}

// ---------------- fused dual-GEMM + bias + tanh transform ----------------
// Per node i, output col j (combined 128 cols: j<64 pos-half, j>=64 neg-half):
//   out[i][j] = sum_k A_h(i,k) * Wc[k][j] + b[j],  z = tanh(out)
// Wc rows [0,KA) from W1 (agg weights), [KA,KA+KB) from W2 (self weights);
// the A operand per half is assembled from P / Q / Zin slices.
// Block = 128 thr: ct = tid&31 -> cols 4ct..4ct+3 (half h = ct>>4),
// g = tid>>5 -> 16 nodes each; 64 nodes per block. K chunked by 64 rows so the
// W stage fits in 32KB static shared. A operands read from global (2 distinct
// 16B addrs per warp-load -> broadcast, L1/L2-served).
template<int KA, int KB>
__global__ __launch_bounds__(128)
void k_transform(const float4* __restrict__ x_or_z, float4* __restrict__ ext_out, int io,
                 const float4* __restrict__ W1p, const float4* __restrict__ W1n,
                 const float4* __restrict__ W2p, const float4* __restrict__ W2n,
                 const float* __restrict__ bpv, const float* __restrict__ bnv)
{
    constexpr int KTOT = KA + KB;
    constexpr int NCH  = KTOT / 64;          // K chunks of 64 rows
    __shared__ float4 Wsh[64 * 32];          // 32 KB

    const float4* __restrict__ Zin = (io == 0) ? x_or_z
                                   : (io == 1 ? (const float4*)d_Z1 : (const float4*)d_Z2);
    float4* __restrict__ Zout = (io == 0) ? (float4*)d_Z1
                              : (io == 1 ? (float4*)d_Z2 : ext_out);

    const int tid  = threadIdx.x;
    const int ct   = tid & 31;
    const int g    = tid >> 5;
    const int h    = ct >> 4;
    const int base = blockIdx.x * 64 + g * 16;           // first node of this thread's 16
    const int nv   = (Nn - base < 16) ? (Nn - base) : 16;  // valid nodes (may be <=0)

    float bb[4];
    #pragma unroll
    for (int c = 0; c < 4; c++) {
        int j = ct * 4 + c;
        bb[c] = (j < 64) ? bpv[j] : bnv[j - 64];
    }

    float acc[16][4];
    #pragma unroll
    for (int m = 0; m < 16; m++) {
        acc[m][0] = 0.f; acc[m][1] = 0.f; acc[m][2] = 0.f; acc[m][3] = 0.f;
    }

    for (int c = 0; c < NCH; c++) {
        __syncthreads();
        // stage W chunk rows [c*64, c*64+64), combined cols (16 float4)
        for (int f = tid; f < 64 * 32; f += 128) {
            int jq = f & 31;
            int k  = c * 64 + (f >> 5);
            float4 v;
            if (jq < 16) v = (k < KA) ? W1p[k * 16 + jq]      : W2p[(k - KA) * 16 + jq];
            else         v = (k < KA) ? W1n[k * 16 + jq - 16] : W2n[(k - KA) * 16 + jq - 16];
            Wsh[f] = v;
        }
        __syncthreads();

        #pragma unroll 4
        for (int kq = 0; kq < 16; kq++) {
            const int KQg = c * 16 + kq;          // global float4-k index
            const float4* aptr;
            if (KTOT == 256) {                    // round 0
                if (KQg < 32) aptr = (h ? d_Q : d_P) + KQg;
                else          aptr = Zin + (KQg - 32);
            } else {                              // rounds 1+
                if (KQg < 16)      aptr = d_P + h * 16 + KQg;
                else if (KQg < 32) aptr = d_Q + (1 - h) * 16 + (KQg - 16);
                else               aptr = Zin + h * 16 + (KQg - 32);
            }
            aptr += (long)base * 32;

            float4 w0 = Wsh[(4 * kq + 0) * 32 + ct];
            float4 w1 = Wsh[(4 * kq + 1) * 32 + ct];
            float4 w2 = Wsh[(4 * kq + 2) * 32 + ct];
            float4 w3 = Wsh[(4 * kq + 3) * 32 + ct];
            #pragma unroll
            for (int m = 0; m < 16; m++) {
                float4 a = (m < nv) ? aptr[m * 32] : make_float4(0.f, 0.f, 0.f, 0.f);
                acc[m][0] += a.x * w0.x + a.y * w1.x + a.z * w2.x + a.w * w3.x;
                acc[m][1] += a.x * w0.y + a.y * w1.y + a.z * w2.y + a.w * w3.y;
                acc[m][2] += a.x * w0.z + a.y * w1.z + a.z * w2.z + a.w * w3.z;
                acc[m][3] += a.x * w0.w + a.y * w1.w + a.z * w2.w + a.w * w3.w;
            }
        }
    }

    #pragma unroll
    for (int m = 0; m < 16; m++) {
        int i = base + m;
        if (m < nv) {
            Zout[(long)i * 32 + ct] = make_float4(tanhf(acc[m][0] + bb[0]),
                                                  tanhf(acc[m][1] + bb[1]),
                                                  tanhf(acc[m][2] + bb[2]),
                                                  tanhf(acc[m][3] + bb[3]));
        }
    }
}

// ---------------- launch (kernel launches only; graph-capturable) ----------------
extern "C" void kernel_launch(void* const* d_in, const int* in_sizes, int n_in,
                              void* d_out, int out_size) {
    const float* x      = (const float*)d_in[0];
    const void*  pe     = d_in[1];     // edge indices: int32 or int64, detected on device
    const void*  ne     = d_in[2];
    const float4* Wp_l  = (const float4*)d_in[3];
    const float4* Wp_r  = (const float4*)d_in[4];
    const float*  bp    = (const float*)d_in[5];
    const float4* Wn_l  = (const float4*)d_in[6];
    const float4* Wn_r  = (const float4*)d_in[7];
    const float*  bn    = (const float*)d_in[8];
    const float4* Wl_pos = (const float4*)d_in[9];
    const float4* Wr_pos = (const float4*)d_in[10];
    const float*  b_pos  = (const float*)d_in[11];
    const float4* Wl_neg = (const float4*)d_in[12];
    const float4* Wr_neg = (const float4*)d_in[13];
    const float*  b_neg  = (const float*)d_in[14];

    // CSR build (per-launch, deterministic)
    k_detect<<<1, 256>>>((const int*)pe);
    k_zero <<<(2 * Nn + 255) / 256, 256>>>();
    k_hist <<<(2 * Ee + 255) / 256, 256>>>(pe, ne);
    k_scan1<<<dim3(98, 2), 1024>>>();
    k_scan2<<<dim3(1, 2), 128>>>();
    k_scan3<<<dim3((Nn + 255) / 256, 2), 256>>>();
    k_fill <<<(2 * Ee + 255) / 256, 256>>>(pe, ne);

    const float4* xin  = (const float4*)x;
    float4*       outp = (float4*)d_out;
    const int TGRID = (Nn + 63) / 64;

    // round 0
    k_agg<<<dim3(Nn / 4, 2), 128>>>(xin, 0);
    k_transform<128, 128><<<TGRID, 128>>>(xin, outp, 0, Wp_l, Wn_l, Wp_r, Wn_r, bp, bn);

    // round 1 (hidden layer l=0)
    k_agg<<<dim3(Nn / 4, 2), 128>>>(xin, 1);
    k_transform<128, 64><<<TGRID, 128>>>(xin, outp, 1,
        Wl_pos, Wl_neg, Wr_pos, Wr_neg, b_pos, b_neg);

    // round 2 (hidden layer l=1) -> writes d_out
    k_agg<<<dim3(Nn / 4, 2), 128>>>(xin, 2);
    k_transform<128, 64><<<TGRID, 128>>>(xin, outp, 2,
        Wl_pos + 2048, Wl_neg + 2048, Wr_pos + 1024, Wr_neg + 1024, b_pos + 64, b_neg + 64);
}

// round 6
// speedup vs baseline: 1.6339x; 1.6339x over previous
#include <cuda_runtime.h>
#include <math.h>

#define Nn 100000
#define Ee 1200000

// ---------------- persistent device scratch (no runtime allocation) ----------------
__device__ int    d_is64;          // 1 if edge indices are int64, 0 if int32
__device__ int    d_cnt[2][Nn];
__device__ int    d_rowstart[2][Nn + 1];
__device__ int    d_cursor[2][Nn];
__device__ int    d_csr[2][Ee];
__device__ float  d_inv[2][Nn];
__device__ int    d_bsum[2][128];
__device__ int    d_bscan[2][128];
__device__ float4 d_P[Nn * 32];    // pos-mean-agg of current features (128 f32 per node)
__device__ float4 d_Q[Nn * 32];    // neg-mean-agg
__device__ float4 d_Z1[Nn * 32];   // z after round 0
__device__ float4 d_Z2[Nn * 32];   // z after round 1

// ---------------- f32x2 packed-FMA helpers ----------------
__device__ __forceinline__ unsigned long long pack2(float lo, float hi) {
    unsigned long long r;
    asm("mov.b64 %0, {%1, %2};" : "=l"(r) : "f"(lo), "f"(hi));
    return r;
}
__device__ __forceinline__ void fma2(unsigned long long& d, unsigned long long a,
                                     unsigned long long b) {
    asm("fma.rn.f32x2 %0, %1, %2, %0;" : "+l"(d) : "l"(a), "l"(b));
}
__device__ __forceinline__ float2 unpack2(unsigned long long v) {
    float2 f;
    asm("mov.b64 {%0, %1}, %2;" : "=f"(f.x), "=f"(f.y) : "l"(v));
    return f;
}

// ---------------- dtype detection ----------------
// If the buffer holds int64 indices (all < 2^31, nonnegative), viewed as int32
// every odd word is 0. With int32 data, 1024 sampled odd words all-zero is
// probabilistically impossible.
__global__ void k_detect(const int* __restrict__ pe) {
    __shared__ int nz;
    if (threadIdx.x == 0) nz = 0;
    __syncthreads();
    for (int t = threadIdx.x; t < 1024; t += blockDim.x) {
        if (pe[2 * t + 1] != 0) nz = 1;
    }
    __syncthreads();
    if (threadIdx.x == 0) d_is64 = (nz == 0) ? 1 : 0;
}

__device__ __forceinline__ int edge_at(const void* p, long i, int is64) {
    return is64 ? (int)((const long long*)p)[i] : ((const int*)p)[i];
}

// ---------------- CSR build ----------------
__global__ void k_zero() {
    int i = blockIdx.x * blockDim.x + threadIdx.x;
    if (i < 2 * Nn) (&d_cnt[0][0])[i] = 0;
}

__global__ void k_hist(const void* __restrict__ pe, const void* __restrict__ ne) {
    int is64 = d_is64;
    int i = blockIdx.x * blockDim.x + threadIdx.x;
    if (i < Ee) {
        int dst = edge_at(pe, (long)Ee + i, is64);
        if ((unsigned)dst < Nn) atomicAdd(&d_cnt[0][dst], 1);
    } else if (i < 2 * Ee) {
        int dst = edge_at(ne, (long)i, is64);
        if ((unsigned)dst < Nn) atomicAdd(&d_cnt[1][dst], 1);
    }
}

__global__ void k_scan1() {
    __shared__ int sh[1024];
    int L = blockIdx.y;
    int i = blockIdx.x * 1024 + threadIdx.x;
    int v = (i < Nn) ? d_cnt[L][i] : 0;
    sh[threadIdx.x] = v;
    __syncthreads();
    for (int off = 1; off < 1024; off <<= 1) {
        int t = (threadIdx.x >= off) ? sh[threadIdx.x - off] : 0;
        __syncthreads();
        sh[threadIdx.x] += t;
        __syncthreads();
    }
    if (i < Nn) d_rowstart[L][i] = sh[threadIdx.x] - v;
    if (threadIdx.x == 1023) d_bsum[L][blockIdx.x] = sh[1023];
}

__global__ void k_scan2() {
    __shared__ int sh[128];
    int L = blockIdx.y;
    int v = (threadIdx.x < 98) ? d_bsum[L][threadIdx.x] : 0;
    sh[threadIdx.x] = v;
    __syncthreads();
    for (int off = 1; off < 128; off <<= 1) {
        int t = (threadIdx.x >= off) ? sh[threadIdx.x - off] : 0;
        __syncthreads();
        sh[threadIdx.x] += t;
        __syncthreads();
    }
    d_bscan[L][threadIdx.x] = sh[threadIdx.x] - v;
}

__global__ void k_scan3() {
    int L = blockIdx.y;
    int i = blockIdx.x * blockDim.x + threadIdx.x;
    if (i < Nn) {
        int rs = d_rowstart[L][i] + d_bscan[L][i >> 10];
        d_rowstart[L][i] = rs;
        d_cursor[L][i]   = rs;
        int c = d_cnt[L][i];
        d_inv[L][i] = 1.0f / (float)(c > 0 ? c : 1);
    }
    if (i == Nn - 1) d_rowstart[L][Nn] = d_rowstart[L][i] + d_cnt[L][i];
}

__global__ void k_fill(const void* __restrict__ pe, const void* __restrict__ ne) {
    int is64 = d_is64;
    int i = blockIdx.x * blockDim.x + threadIdx.x;
    if (i < Ee) {
        int s = edge_at(pe, (long)i, is64);
        int d = edge_at(pe, (long)Ee + i, is64);
        if ((unsigned)d < Nn && (unsigned)s < Nn)
            d_csr[0][atomicAdd(&d_cursor[0][d], 1)] = s;
    } else if (i < 2 * Ee) {
        long k = i - Ee;
        int s = edge_at(ne, k, is64);
        int d = edge_at(ne, (long)i, is64);
        if ((unsigned)d < Nn && (unsigned)s < Nn)
            d_csr[1][atomicAdd(&d_cursor[1][d], 1)] = s;
    }
}

// ---------------- per-destination mean aggregation (atomic-free) ----------------
__global__ void k_agg(const float4* __restrict__ ext, int io) {
    const float4* __restrict__ Zin = (io == 0) ? ext
                                   : (io == 1 ? (const float4*)d_Z1 : (const float4*)d_Z2);
    int L    = blockIdx.y;
    int node = blockIdx.x * 4 + (threadIdx.x >> 5);
    int lane = threadIdx.x & 31;
    int s = d_rowstart[L][node];
    int e = d_rowstart[L][node + 1];
    const int* __restrict__ csr = d_csr[L];
    float ax = 0.f, ay = 0.f, az = 0.f, aw = 0.f;
    int j = s;
    for (; j + 4 <= e; j += 4) {
        int s0 = csr[j], s1 = csr[j + 1], s2 = csr[j + 2], s3 = csr[j + 3];
        float4 v0 = Zin[s0 * 32 + lane];
        float4 v1 = Zin[s1 * 32 + lane];
        float4 v2 = Zin[s2 * 32 + lane];
        float4 v3 = Zin[s3 * 32 + lane];
        ax += v0.x + v1.x + v2.x + v3.x;
        ay += v0.y + v1.y + v2.y + v3.y;
        az += v0.z + v1.z + v2.z + v3.z;
        aw += v0.w + v1.w + v2.w + v3.w;
    }
    for (; j < e; j++) {
        float4 v = Zin[csr[j] * 32 + lane];
        ax += v.x; ay += v.y; az += v.z; aw += v.w;
    }
    float iv = d_inv[L][node];
    (L ? d_Q : d_P)[node * 32 + lane] = make_float4(ax * iv, ay * iv, az * iv, aw * iv);
}

// ---------------- fused dual-GEMM + bias + tanh (f32x2 packed FMA) ----------------
// 64 nodes per block. ct = tid&31 -> cols 4ct..4ct+3 (half h = ct>>4),
// g = tid>>5 -> 16 nodes. K processed in chunks of 16 rows:
//   Wsh  : [16 k-rows][32 float4]  -> ulonglong2 loads give (c0,c1),(c2,c3) pairs free.
//   Adup : per (node, h, k) the A value PRE-DUPLICATED as f32x2 -> mainloop has
//          zero packing MOVs; 2 fma2 per 4 scalar FMAs.
template<int KA, int KB>
__global__ __launch_bounds__(128)
void k_transform(const float4* __restrict__ x_or_z, float4* __restrict__ ext_out, int io,
                 const float4* __restrict__ W1p, const float4* __restrict__ W1n,
                 const float4* __restrict__ W2p, const float4* __restrict__ W2n,
                 const float* __restrict__ bpv, const float* __restrict__ bnv)
{
    constexpr int KTOT = KA + KB;
    constexpr int NCH  = KTOT / 16;
    __shared__ float4     Wsh[16][32];        // 8 KB
    __shared__ ulonglong2 Adup[64][2][8];     // 16 KB: [n][h][k-pair], dup'd f32x2

    const float4* __restrict__ Zin = (io == 0) ? x_or_z
                                   : (io == 1 ? (const float4*)d_Z1 : (const float4*)d_Z2);
    float4* __restrict__ Zout = (io == 0) ? (float4*)d_Z1
                              : (io == 1 ? (float4*)d_Z2 : ext_out);

    const int tid  = threadIdx.x;
    const int ct   = tid & 31;
    const int g    = tid >> 5;
    const int h    = ct >> 4;
    const int base = blockIdx.x * 64;

    unsigned long long acc[16][2];
    {
        int j0 = ct * 4;
        float b0 = (j0 + 0 < 64) ? bpv[j0 + 0] : bnv[j0 - 64];
        float b1 = (j0 + 1 < 64) ? bpv[j0 + 1] : bnv[j0 - 63];
        float b2 = (j0 + 2 < 64) ? bpv[j0 + 2] : bnv[j0 - 62];
        float b3 = (j0 + 3 < 64) ? bpv[j0 + 3] : bnv[j0 - 61];
        unsigned long long p01 = pack2(b0, b1), p23 = pack2(b2, b3);
        #pragma unroll
        for (int m = 0; m < 16; m++) { acc[m][0] = p01; acc[m][1] = p23; }
    }

    for (int c = 0; c < NCH; c++) {
        __syncthreads();
        // stage W chunk rows [c*16, c*16+16)
        for (int f = tid; f < 16 * 32; f += 128) {
            int jq = f & 31, r = f >> 5;
            int k  = c * 16 + r;
            float4 v;
            if (jq < 16) v = (k < KA) ? W1p[k * 16 + jq]      : W2p[(k - KA) * 16 + jq];
            else         v = (k < KA) ? W1n[k * 16 + jq - 16] : W2n[(k - KA) * 16 + jq - 16];
            Wsh[r][jq] = v;
        }
        // stage Adup: 64 nodes x 2 halves x 4 float4-k per chunk
        for (int f = tid; f < 512; f += 128) {
            int kk4 = f & 3;
            int hh  = (f >> 2) & 1;
            int n   = f >> 3;
            int i   = base + n;
            int KQg = c * 4 + kk4;
            float4 v = make_float4(0.f, 0.f, 0.f, 0.f);
            if (i < Nn) {
                const float4* ap;
                if (KTOT == 256) {                    // round 0
                    if (KQg < 32) ap = (hh ? d_Q : d_P) + (long)i * 32 + KQg;
                    else          ap = Zin + (long)i * 32 + (KQg - 32);
                } else {                              // rounds 1+
                    if (KQg < 16)      ap = d_P + (long)i * 32 + hh * 16 + KQg;
                    else if (KQg < 32) ap = d_Q + (long)i * 32 + (1 - hh) * 16 + (KQg - 16);
                    else               ap = Zin + (long)i * 32 + hh * 16 + (KQg - 32);
                }
                v = *ap;
            }
            ulonglong2 p0, p1;
            p0.x = pack2(v.x, v.x); p0.y = pack2(v.y, v.y);
            p1.x = pack2(v.z, v.z); p1.y = pack2(v.w, v.w);
            Adup[n][hh][kk4 * 2 + 0] = p0;
            Adup[n][hh][kk4 * 2 + 1] = p1;
        }
        __syncthreads();

        #pragma unroll
        for (int kq = 0; kq < 4; kq++) {
            ulonglong2 w0 = *(const ulonglong2*)&Wsh[4 * kq + 0][ct];
            ulonglong2 w1 = *(const ulonglong2*)&Wsh[4 * kq + 1][ct];
            ulonglong2 w2 = *(const ulonglong2*)&Wsh[4 * kq + 2][ct];
            ulonglong2 w3 = *(const ulonglong2*)&Wsh[4 * kq + 3][ct];
            #pragma unroll
            for (int m = 0; m < 16; m++) {
                ulonglong2 a01 = Adup[g * 16 + m][h][kq * 2 + 0];
                ulonglong2 a23 = Adup[g * 16 + m][h][kq * 2 + 1];
                fma2(acc[m][0], a01.x, w0.x);
                fma2(acc[m][1], a01.x, w0.y);
                fma2(acc[m][0], a01.y, w1.x);
                fma2(acc[m][1], a01.y, w1.y);
                fma2(acc[m][0], a23.x, w2.x);
                fma2(acc[m][1], a23.x, w2.y);
                fma2(acc[m][0], a23.y, w3.x);
                fma2(acc[m][1], a23.y, w3.y);
            }
        }
    }

    #pragma unroll
    for (int m = 0; m < 16; m++) {
        int i = base + g * 16 + m;
        if (i < Nn) {
            float2 r01 = unpack2(acc[m][0]);
            float2 r23 = unpack2(acc[m][1]);
            Zout[(long)i * 32 + ct] = make_float4(tanhf(r01.x), tanhf(r01.y),
                                                  tanhf(r23.x), tanhf(r23.y));
        }
    }
}

// ---------------- launch (kernel launches only; graph-capturable) ----------------
extern "C" void kernel_launch(void* const* d_in, const int* in_sizes, int n_in,
                              void* d_out, int out_size) {
    const float* x      = (const float*)d_in[0];
    const void*  pe     = d_in[1];     // edge indices: int32 or int64, detected on device
    const void*  ne     = d_in[2];
    const float4* Wp_l  = (const float4*)d_in[3];
    const float4* Wp_r  = (const float4*)d_in[4];
    const float*  bp    = (const float*)d_in[5];
    const float4* Wn_l  = (const float4*)d_in[6];
    const float4* Wn_r  = (const float4*)d_in[7];
    const float*  bn    = (const float*)d_in[8];
    const float4* Wl_pos = (const float4*)d_in[9];
    const float4* Wr_pos = (const float4*)d_in[10];
    const float*  b_pos  = (const float*)d_in[11];
    const float4* Wl_neg = (const float4*)d_in[12];
    const float4* Wr_neg = (const float4*)d_in[13];
    const float*  b_neg  = (const float*)d_in[14];

    // CSR build (per-launch, deterministic)
    k_detect<<<1, 256>>>((const int*)pe);
    k_zero <<<(2 * Nn + 255) / 256, 256>>>();
    k_hist <<<(2 * Ee + 255) / 256, 256>>>(pe, ne);
    k_scan1<<<dim3(98, 2), 1024>>>();
    k_scan2<<<dim3(1, 2), 128>>>();
    k_scan3<<<dim3((Nn + 255) / 256, 2), 256>>>();
    k_fill <<<(2 * Ee + 255) / 256, 256>>>(pe, ne);

    const float4* xin  = (const float4*)x;
    float4*       outp = (float4*)d_out;
    const int TGRID = (Nn + 63) / 64;

    // round 0
    k_agg<<<dim3(Nn / 4, 2), 128>>>(xin, 0);
    k_transform<128, 128><<<TGRID, 128>>>(xin, outp, 0, Wp_l, Wn_l, Wp_r, Wn_r, bp, bn);

    // round 1 (hidden layer l=0)
    k_agg<<<dim3(Nn / 4, 2), 128>>>(xin, 1);
    k_transform<128, 64><<<TGRID, 128>>>(xin, outp, 1,
        Wl_pos, Wl_neg, Wr_pos, Wr_neg, b_pos, b_neg);

    // round 2 (hidden layer l=1) -> writes d_out
    k_agg<<<dim3(Nn / 4, 2), 128>>>(xin, 2);
    k_transform<128, 64><<<TGRID, 128>>>(xin, outp, 2,
        Wl_pos + 2048, Wl_neg + 2048, Wr_pos + 1024, Wr_neg + 1024, b_pos + 64, b_neg + 64);
}

// round 7
// speedup vs baseline: 1.6613x; 1.0168x over previous
#include <cuda_runtime.h>
#include <cuda_fp16.h>
#include <math.h>

#define Nn 100000
#define Ee 1200000

// ---------------- persistent device scratch (no runtime allocation) ----------------
__device__ int    d_is64;          // 1 if edge indices are int64, 0 if int32
__device__ int    d_cnt[2][Nn];
__device__ int    d_rowstart[2][Nn + 1];
__device__ int    d_cursor[2][Nn];
__device__ int    d_csr[2][Ee];
__device__ float  d_inv[2][Nn];
__device__ int    d_bsum[2][128];
__device__ int    d_bscan[2][128];
__device__ float4 d_P[Nn * 32];    // pos-mean-agg (fp32, 128 per node)
__device__ float4 d_Q[Nn * 32];    // neg-mean-agg
__device__ float4 d_Z1[Nn * 32];   // z after round 0 (fp32)
__device__ float4 d_Z2[Nn * 32];   // z after round 1 (fp32)
__device__ uint2  d_Xh [Nn * 32];  // fp16 mirror of x   (4 halfs per uint2)
__device__ uint2  d_Zh1[Nn * 32];  // fp16 mirror of z1
__device__ uint2  d_Zh2[Nn * 32];  // fp16 mirror of z2

// ---------------- f32x2 packed-FMA helpers ----------------
__device__ __forceinline__ unsigned long long pack2(float lo, float hi) {
    unsigned long long r;
    asm("mov.b64 %0, {%1, %2};" : "=l"(r) : "f"(lo), "f"(hi));
    return r;
}
__device__ __forceinline__ void fma2(unsigned long long& d, unsigned long long a,
                                     unsigned long long b) {
    asm("fma.rn.f32x2 %0, %1, %2, %0;" : "+l"(d) : "l"(a), "l"(b));
}
__device__ __forceinline__ float2 unpack2(unsigned long long v) {
    float2 f;
    asm("mov.b64 {%0, %1}, %2;" : "=f"(f.x), "=f"(f.y) : "l"(v));
    return f;
}

// ---------------- dtype detection (int64 vs int32 edge indices) ----------------
__global__ void k_detect(const int* __restrict__ pe) {
    __shared__ int nz;
    if (threadIdx.x == 0) nz = 0;
    __syncthreads();
    for (int t = threadIdx.x; t < 1024; t += blockDim.x) {
        if (pe[2 * t + 1] != 0) nz = 1;
    }
    __syncthreads();
    if (threadIdx.x == 0) d_is64 = (nz == 0) ? 1 : 0;
}

__device__ __forceinline__ int edge_at(const void* p, long i, int is64) {
    return is64 ? (int)((const long long*)p)[i] : ((const int*)p)[i];
}

// ---------------- fp32 -> fp16 mirror of x ----------------
__global__ void k_x2h(const float4* __restrict__ x) {
    long i = (long)blockIdx.x * blockDim.x + threadIdx.x;
    if (i < (long)Nn * 32) {
        float4 v = x[i];
        __half2 a = __floats2half2_rn(v.x, v.y);
        __half2 b = __floats2half2_rn(v.z, v.w);
        uint2 o;
        o.x = *(const unsigned*)&a;
        o.y = *(const unsigned*)&b;
        d_Xh[i] = o;
    }
}

// ---------------- CSR build ----------------
__global__ void k_zero() {
    int i = blockIdx.x * blockDim.x + threadIdx.x;
    if (i < 2 * Nn) (&d_cnt[0][0])[i] = 0;
}

__global__ void k_hist(const void* __restrict__ pe, const void* __restrict__ ne) {
    int is64 = d_is64;
    int i = blockIdx.x * blockDim.x + threadIdx.x;
    if (i < Ee) {
        int dst = edge_at(pe, (long)Ee + i, is64);
        if ((unsigned)dst < Nn) atomicAdd(&d_cnt[0][dst], 1);
    } else if (i < 2 * Ee) {
        int dst = edge_at(ne, (long)i, is64);
        if ((unsigned)dst < Nn) atomicAdd(&d_cnt[1][dst], 1);
    }
}

__global__ void k_scan1() {
    __shared__ int sh[1024];
    int L = blockIdx.y;
    int i = blockIdx.x * 1024 + threadIdx.x;
    int v = (i < Nn) ? d_cnt[L][i] : 0;
    sh[threadIdx.x] = v;
    __syncthreads();
    for (int off = 1; off < 1024; off <<= 1) {
        int t = (threadIdx.x >= off) ? sh[threadIdx.x - off] : 0;
        __syncthreads();
        sh[threadIdx.x] += t;
        __syncthreads();
    }
    if (i < Nn) d_rowstart[L][i] = sh[threadIdx.x] - v;
    if (threadIdx.x == 1023) d_bsum[L][blockIdx.x] = sh[1023];
}

__global__ void k_scan2() {
    __shared__ int sh[128];
    int L = blockIdx.y;
    int v = (threadIdx.x < 98) ? d_bsum[L][threadIdx.x] : 0;
    sh[threadIdx.x] = v;
    __syncthreads();
    for (int off = 1; off < 128; off <<= 1) {
        int t = (threadIdx.x >= off) ? sh[threadIdx.x - off] : 0;
        __syncthreads();
        sh[threadIdx.x] += t;
        __syncthreads();
    }
    d_bscan[L][threadIdx.x] = sh[threadIdx.x] - v;
}

__global__ void k_scan3() {
    int L = blockIdx.y;
    int i = blockIdx.x * blockDim.x + threadIdx.x;
    if (i < Nn) {
        int rs = d_rowstart[L][i] + d_bscan[L][i >> 10];
        d_rowstart[L][i] = rs;
        d_cursor[L][i]   = rs;
        int c = d_cnt[L][i];
        d_inv[L][i] = 1.0f / (float)(c > 0 ? c : 1);
    }
    if (i == Nn - 1) d_rowstart[L][Nn] = d_rowstart[L][i] + d_cnt[L][i];
}

__global__ void k_fill(const void* __restrict__ pe, const void* __restrict__ ne) {
    int is64 = d_is64;
    int i = blockIdx.x * blockDim.x + threadIdx.x;
    if (i < Ee) {
        int s = edge_at(pe, (long)i, is64);
        int d = edge_at(pe, (long)Ee + i, is64);
        if ((unsigned)d < Nn && (unsigned)s < Nn)
            d_csr[0][atomicAdd(&d_cursor[0][d], 1)] = s;
    } else if (i < 2 * Ee) {
        long k = i - Ee;
        int s = edge_at(ne, k, is64);
        int d = edge_at(ne, (long)i, is64);
        if ((unsigned)d < Nn && (unsigned)s < Nn)
            d_csr[1][atomicAdd(&d_cursor[1][d], 1)] = s;
    }
}

// ---------------- per-destination mean aggregation (fp16 gathers, fp32 accum) ---
// grid (Nn/4, 2), block 128: warp per dst node, lane covers 4 halfs (8 B).
__global__ void k_agg(int io) {
    const uint2* __restrict__ Zh = (io == 0) ? d_Xh : (io == 1 ? d_Zh1 : d_Zh2);
    int L    = blockIdx.y;
    int node = blockIdx.x * 4 + (threadIdx.x >> 5);
    int lane = threadIdx.x & 31;
    int s = d_rowstart[L][node];
    int e = d_rowstart[L][node + 1];
    const int* __restrict__ csr = d_csr[L];
    float ax = 0.f, ay = 0.f, az = 0.f, aw = 0.f;
    int j = s;
    for (; j + 4 <= e; j += 4) {
        int s0 = csr[j], s1 = csr[j + 1], s2 = csr[j + 2], s3 = csr[j + 3];
        uint2 v0 = Zh[s0 * 32 + lane];
        uint2 v1 = Zh[s1 * 32 + lane];
        uint2 v2 = Zh[s2 * 32 + lane];
        uint2 v3 = Zh[s3 * 32 + lane];
        #pragma unroll
        for (int t = 0; t < 4; t++) {
            uint2 v = (t == 0) ? v0 : (t == 1) ? v1 : (t == 2) ? v2 : v3;
            float2 f01 = __half22float2(*(const __half2*)&v.x);
            float2 f23 = __half22float2(*(const __half2*)&v.y);
            ax += f01.x; ay += f01.y; az += f23.x; aw += f23.y;
        }
    }
    for (; j < e; j++) {
        uint2 v = Zh[csr[j] * 32 + lane];
        float2 f01 = __half22float2(*(const __half2*)&v.x);
        float2 f23 = __half22float2(*(const __half2*)&v.y);
        ax += f01.x; ay += f01.y; az += f23.x; aw += f23.y;
    }
    float iv = d_inv[L][node];
    (L ? d_Q : d_P)[node * 32 + lane] = make_float4(ax * iv, ay * iv, az * iv, aw * iv);
}

// ---------------- fused dual-GEMM + bias + tanh (f32x2 packed FMA) ----------------
template<int KA, int KB>
__global__ __launch_bounds__(128)
void k_transform(const float4* __restrict__ x_or_z, float4* __restrict__ ext_out, int io,
                 const float4* __restrict__ W1p, const float4* __restrict__ W1n,
                 const float4* __restrict__ W2p, const float4* __restrict__ W2n,
                 const float* __restrict__ bpv, const float* __restrict__ bnv)
{
    constexpr int KTOT = KA + KB;
    constexpr int NCH  = KTOT / 16;
    __shared__ float4     Wsh[16][32];        // 8 KB
    __shared__ ulonglong2 Adup[64][2][8];     // 16 KB: [n][h][k-pair], dup'd f32x2

    const float4* __restrict__ Zin = (io == 0) ? x_or_z
                                   : (io == 1 ? (const float4*)d_Z1 : (const float4*)d_Z2);
    float4* __restrict__ Zout = (io == 0) ? (float4*)d_Z1
                              : (io == 1 ? (float4*)d_Z2 : ext_out);
    uint2* __restrict__ Zhout = (io == 0) ? d_Zh1 : (io == 1 ? d_Zh2 : (uint2*)0);

    const int tid  = threadIdx.x;
    const int ct   = tid & 31;
    const int g    = tid >> 5;
    const int h    = ct >> 4;
    const int base = blockIdx.x * 64;

    unsigned long long acc[16][2];
    {
        int j0 = ct * 4;
        float b0 = (j0 + 0 < 64) ? bpv[j0 + 0] : bnv[j0 - 64];
        float b1 = (j0 + 1 < 64) ? bpv[j0 + 1] : bnv[j0 - 63];
        float b2 = (j0 + 2 < 64) ? bpv[j0 + 2] : bnv[j0 - 62];
        float b3 = (j0 + 3 < 64) ? bpv[j0 + 3] : bnv[j0 - 61];
        unsigned long long p01 = pack2(b0, b1), p23 = pack2(b2, b3);
        #pragma unroll
        for (int m = 0; m < 16; m++) { acc[m][0] = p01; acc[m][1] = p23; }
    }

    for (int c = 0; c < NCH; c++) {
        __syncthreads();
        // stage W chunk rows [c*16, c*16+16)
        for (int f = tid; f < 16 * 32; f += 128) {
            int jq = f & 31, r = f >> 5;
            int k  = c * 16 + r;
            float4 v;
            if (jq < 16) v = (k < KA) ? W1p[k * 16 + jq]      : W2p[(k - KA) * 16 + jq];
            else         v = (k < KA) ? W1n[k * 16 + jq - 16] : W2n[(k - KA) * 16 + jq - 16];
            Wsh[r][jq] = v;
        }
        // stage Adup: 64 nodes x 2 halves x 4 float4-k per chunk
        for (int f = tid; f < 512; f += 128) {
            int kk4 = f & 3;
            int hh  = (f >> 2) & 1;
            int n   = f >> 3;
            int i   = base + n;
            int KQg = c * 4 + kk4;
            float4 v = make_float4(0.f, 0.f, 0.f, 0.f);
            if (i < Nn) {
                const float4* ap;
                if (KTOT == 256) {                    // round 0
                    if (KQg < 32) ap = (hh ? d_Q : d_P) + (long)i * 32 + KQg;
                    else          ap = Zin + (long)i * 32 + (KQg - 32);
                } else {                              // rounds 1+
                    if (KQg < 16)      ap = d_P + (long)i * 32 + hh * 16 + KQg;
                    else if (KQg < 32) ap = d_Q + (long)i * 32 + (1 - hh) * 16 + (KQg - 16);
                    else               ap = Zin + (long)i * 32 + hh * 16 + (KQg - 32);
                }
                v = *ap;
            }
            ulonglong2 p0, p1;
            p0.x = pack2(v.x, v.x); p0.y = pack2(v.y, v.y);
            p1.x = pack2(v.z, v.z); p1.y = pack2(v.w, v.w);
            Adup[n][hh][kk4 * 2 + 0] = p0;
            Adup[n][hh][kk4 * 2 + 1] = p1;
        }
        __syncthreads();

        #pragma unroll
        for (int kq = 0; kq < 4; kq++) {
            ulonglong2 w0 = *(const ulonglong2*)&Wsh[4 * kq + 0][ct];
            ulonglong2 w1 = *(const ulonglong2*)&Wsh[4 * kq + 1][ct];
            ulonglong2 w2 = *(const ulonglong2*)&Wsh[4 * kq + 2][ct];
            ulonglong2 w3 = *(const ulonglong2*)&Wsh[4 * kq + 3][ct];
            #pragma unroll
            for (int m = 0; m < 16; m++) {
                ulonglong2 a01 = Adup[g * 16 + m][h][kq * 2 + 0];
                ulonglong2 a23 = Adup[g * 16 + m][h][kq * 2 + 1];
                fma2(acc[m][0], a01.x, w0.x);
                fma2(acc[m][1], a01.x, w0.y);
                fma2(acc[m][0], a01.y, w1.x);
                fma2(acc[m][1], a01.y, w1.y);
                fma2(acc[m][0], a23.x, w2.x);
                fma2(acc[m][1], a23.x, w2.y);
                fma2(acc[m][0], a23.y, w3.x);
                fma2(acc[m][1], a23.y, w3.y);
            }
        }
    }

    #pragma unroll
    for (int m = 0; m < 16; m++) {
        int i = base + g * 16 + m;
        if (i < Nn) {
            float2 r01 = unpack2(acc[m][0]);
            float2 r23 = unpack2(acc[m][1]);
            float t0 = tanhf(r01.x), t1 = tanhf(r01.y);
            float t2 = tanhf(r23.x), t3 = tanhf(r23.y);
            Zout[(long)i * 32 + ct] = make_float4(t0, t1, t2, t3);
            if (Zhout) {
                __half2 a = __floats2half2_rn(t0, t1);
                __half2 b = __floats2half2_rn(t2, t3);
                uint2 o;
                o.x = *(const unsigned*)&a;
                o.y = *(const unsigned*)&b;
                Zhout[(long)i * 32 + ct] = o;
            }
        }
    }
}

// ---------------- launch (kernel launches only; graph-capturable) ----------------
extern "C" void kernel_launch(void* const* d_in, const int* in_sizes, int n_in,
                              void* d_out, int out_size) {
    const float* x      = (const float*)d_in[0];
    const void*  pe     = d_in[1];     // edge indices: int32 or int64, detected on device
    const void*  ne     = d_in[2];
    const float4* Wp_l  = (const float4*)d_in[3];
    const float4* Wp_r  = (const float4*)d_in[4];
    const float*  bp    = (const float*)d_in[5];
    const float4* Wn_l  = (const float4*)d_in[6];
    const float4* Wn_r  = (const float4*)d_in[7];
    const float*  bn    = (const float*)d_in[8];
    const float4* Wl_pos = (const float4*)d_in[9];
    const float4* Wr_pos = (const float4*)d_in[10];
    const float*  b_pos  = (const float*)d_in[11];
    const float4* Wl_neg = (const float4*)d_in[12];
    const float4* Wr_neg = (const float4*)d_in[13];
    const float*  b_neg  = (const float*)d_in[14];

    const float4* xin  = (const float4*)x;
    float4*       outp = (float4*)d_out;

    // CSR build + fp16 mirror of x
    k_detect<<<1, 256>>>((const int*)pe);
    k_x2h  <<<(Nn * 32 + 255) / 256, 256>>>(xin);
    k_zero <<<(2 * Nn + 255) / 256, 256>>>();
    k_hist <<<(2 * Ee + 255) / 256, 256>>>(pe, ne);
    k_scan1<<<dim3(98, 2), 1024>>>();
    k_scan2<<<dim3(1, 2), 128>>>();
    k_scan3<<<dim3((Nn + 255) / 256, 2), 256>>>();
    k_fill <<<(2 * Ee + 255) / 256, 256>>>(pe, ne);

    const int TGRID = (Nn + 63) / 64;

    // round 0
    k_agg<<<dim3(Nn / 4, 2), 128>>>(0);
    k_transform<128, 128><<<TGRID, 128>>>(xin, outp, 0, Wp_l, Wn_l, Wp_r, Wn_r, bp, bn);

    // round 1 (hidden layer l=0)
    k_agg<<<dim3(Nn / 4, 2), 128>>>(1);
    k_transform<128, 64><<<TGRID, 128>>>(xin, outp, 1,
        Wl_pos, Wl_neg, Wr_pos, Wr_neg, b_pos, b_neg);

    // round 2 (hidden layer l=1) -> writes d_out
    k_agg<<<dim3(Nn / 4, 2), 128>>>(2);
    k_transform<128, 64><<<TGRID, 128>>>(xin, outp, 2,
        Wl_pos + 2048, Wl_neg + 2048, Wr_pos + 1024, Wr_neg + 1024, b_pos + 64, b_neg + 64);
}